// round 14
// baseline (speedup 1.0000x reference)
#include <cuda_runtime.h>
#include <cuda_bf16.h>
#include <cuda_fp16.h>
#include <cstdint>

#define NB 8
#define LSEQ 2048
#define DIM 128
#define NSPLIT 2
#define KSPLIT (LSEQ / NSPLIT)   // 1024

// 64 MiB: Ê fp16 pairs, layout [b][m][cpair]
static __device__ uint32_t g_E16[(size_t)NB * LSEQ * 1024];
// 4 MiB: ctx transposed fp16 pairs [b][d][cpair]
static __device__ uint32_t g_Ct16[(size_t)NB * DIM * 1024];
// 16 MiB split-K partials of GEMM2: [split][b][m][d]
static __device__ float g_part[(size_t)NSPLIT * NB * LSEQ * DIM];
// per-(b,c)-row per-m-tile partial sums and maxes of E
static __device__ float g_esum[(size_t)NB * LSEQ * 16];
static __device__ float g_emax[(size_t)NB * LSEQ * 16];
// fp16 f-pairs: f(c,mt)=mu(c,mt)/sum(c); word [b][mt][cpair]
static __device__ uint32_t g_f16[(size_t)NB * 16 * 1024];
// completion flags for fused split-K reduction (one per (b, mtile))
static __device__ int g_flag[NB * 16];
// pre-converted bf16 hi/lo limb words for gemm1 inputs
#define NWORDS ((size_t)NB * LSEQ * DIM / 2)
static __device__ uint32_t g_cth[NWORDS];
static __device__ uint32_t g_ctl[NWORDS];
static __device__ uint32_t g_mnh[NWORDS];
static __device__ uint32_t g_mnl[NWORDS];

__device__ __forceinline__ uint32_t pack_bf16x2(float x, float y) {
    __nv_bfloat162 h = __floats2bfloat162_rn(x, y);
    return *reinterpret_cast<uint32_t*>(&h);
}
__device__ __forceinline__ uint32_t pack_half2(float x, float y) {
    __half2 h = __floats2half2_rn(x, y);
    return *reinterpret_cast<uint32_t*>(&h);
}
__device__ __forceinline__ uint32_t hmul2u(uint32_t a, uint32_t b) {
    __half2 r = __hmul2(*reinterpret_cast<__half2*>(&a), *reinterpret_cast<__half2*>(&b));
    return *reinterpret_cast<uint32_t*>(&r);
}

#define MMA_BF16(d, a, b0v, b1v)                                               \
    asm volatile(                                                              \
        "mma.sync.aligned.m16n8k16.row.col.f32.bf16.bf16.f32 "                 \
        "{%0,%1,%2,%3}, {%4,%5,%6,%7}, {%8,%9}, {%0,%1,%2,%3};"                \
        : "+f"((d)[0]), "+f"((d)[1]), "+f"((d)[2]), "+f"((d)[3])               \
        : "r"((a)[0]), "r"((a)[1]), "r"((a)[2]), "r"((a)[3]),                  \
          "r"(b0v), "r"(b1v))

#define MMA_F16(d, a, b0v, b1v)                                                \
    asm volatile(                                                              \
        "mma.sync.aligned.m16n8k16.row.col.f32.f16.f16.f32 "                   \
        "{%0,%1,%2,%3}, {%4,%5,%6,%7}, {%8,%9}, {%0,%1,%2,%3};"                \
        : "+f"((d)[0]), "+f"((d)[1]), "+f"((d)[2]), "+f"((d)[3])               \
        : "r"((a)[0]), "r"((a)[1]), "r"((a)[2]), "r"((a)[3]),                  \
          "r"(b0v), "r"(b1v))

#define LDSM4(r0, r1, r2, r3, addr)                                            \
    asm volatile("ldmatrix.sync.aligned.m8n8.x4.shared.b16 {%0,%1,%2,%3}, [%4];" \
                 : "=r"(r0), "=r"(r1), "=r"(r2), "=r"(r3) : "r"(addr))

#define CP16(dst, src)                                                         \
    asm volatile("cp.async.cg.shared.global [%0], [%1], 16;"                   \
                 :: "r"(dst), "l"(src))
#define CP_COMMIT() asm volatile("cp.async.commit_group;")
#define CP_WAIT1() asm volatile("cp.async.wait_group 1;")
#define CP_WAIT0() asm volatile("cp.async.wait_group 0;")

// ---------------------------------------------------------------------------
// precvt: split ctx/main into bf16 hi + lo limb word arrays (gemm1 inputs).
// ---------------------------------------------------------------------------
__global__ __launch_bounds__(256) void precvt_kernel(const float* __restrict__ ctx,
                                                     const float* __restrict__ mn) {
    const size_t i = (size_t)blockIdx.x * 256 + threadIdx.x;  // float4 index
    {
        float4 v = ((const float4*)ctx)[i];
        uint32_t h01 = pack_bf16x2(v.x, v.y);
        uint32_t h23 = pack_bf16x2(v.z, v.w);
        __nv_bfloat162 hp = *(__nv_bfloat162*)&h01;
        __nv_bfloat162 hq = *(__nv_bfloat162*)&h23;
        g_cth[2 * i]     = h01;
        g_cth[2 * i + 1] = h23;
        g_ctl[2 * i]     = pack_bf16x2(v.x - __bfloat162float(hp.x),
                                       v.y - __bfloat162float(hp.y));
        g_ctl[2 * i + 1] = pack_bf16x2(v.z - __bfloat162float(hq.x),
                                       v.w - __bfloat162float(hq.y));
    }
    {
        float4 v = ((const float4*)mn)[i];
        uint32_t h01 = pack_bf16x2(v.x, v.y);
        uint32_t h23 = pack_bf16x2(v.z, v.w);
        __nv_bfloat162 hp = *(__nv_bfloat162*)&h01;
        __nv_bfloat162 hq = *(__nv_bfloat162*)&h23;
        g_mnh[2 * i]     = h01;
        g_mnh[2 * i + 1] = h23;
        g_mnl[2 * i]     = pack_bf16x2(v.x - __bfloat162float(hp.x),
                                       v.y - __bfloat162float(hp.y));
        g_mnl[2 * i + 1] = pack_bf16x2(v.z - __bfloat162float(hq.x),
                                       v.w - __bfloat162float(hq.y));
    }
}

// ---------------------------------------------------------------------------
// tctx: g_Ct16[b][d][cp] = (half(ctx[b,2cp,d]), half(ctx[b,2cp+1,d]))
// ---------------------------------------------------------------------------
__global__ __launch_bounds__(256) void tctx_kernel(const float* __restrict__ ctx) {
    const int b  = blockIdx.x >> 4;
    const int ct = blockIdx.x & 15;
    const int t  = threadIdx.x;
    const int cp = t & 63;
    const int d0 = (t >> 6) * 32;
    const float* r0 = ctx + ((size_t)b * LSEQ + ct * 128 + 2 * cp) * DIM + d0;
    const float* r1 = r0 + DIM;
#pragma unroll
    for (int j = 0; j < 8; j++) {
        float4 a = ((const float4*)r0)[j];
        float4 c = ((const float4*)r1)[j];
        const size_t base = ((size_t)(b * DIM + d0 + 4 * j)) * 1024 + ct * 64 + cp;
        g_Ct16[base]        = pack_half2(a.x, c.x);
        g_Ct16[base + 1024] = pack_half2(a.y, c.y);
        g_Ct16[base + 2048] = pack_half2(a.z, c.z);
        g_Ct16[base + 3072] = pack_half2(a.w, c.w);
    }
}

// ---------------------------------------------------------------------------
// GEMM1 (bf16 m16n8k16 3x split, cp.async 2-stage, ldmatrix fragments).
// Epilogue: exp, per-tile row max/sum, store Ê fp16 TRANSPOSED [m][cpair].
// ---------------------------------------------------------------------------
#define WS1 20
#define TILE_W (128 * WS1)
#define STAGE_W (4 * TILE_W)
#define SMEM1_BYTES (2 * STAGE_W * 4)        // 81920

__global__ __launch_bounds__(256, 2) void gemm1_mma() {
    extern __shared__ uint32_t sm1[];
    const int tid  = threadIdx.x;
    const int wid  = tid >> 5;
    const int lane = tid & 31;
    const int wm   = (wid >> 2) * 64;
    const int wn   = (wid & 3) * 32;
    const int lr4  = lane >> 2;
    const int lk4  = lane & 3;

    const int b  = blockIdx.z;
    const int c0 = blockIdx.y * 128;
    const int m0 = blockIdx.x * 128;

    const uint32_t* AH = g_cth + ((size_t)b * LSEQ + c0) * (DIM / 2);
    const uint32_t* AL = g_ctl + ((size_t)b * LSEQ + c0) * (DIM / 2);
    const uint32_t* BH = g_mnh + ((size_t)b * LSEQ + m0) * (DIM / 2);
    const uint32_t* BL = g_mnl + ((size_t)b * LSEQ + m0) * (DIM / 2);

    uint32_t sb;
    asm("{ .reg .u64 t; cvta.to.shared.u64 t, %1; cvt.u32.u64 %0, t; }"
        : "=r"(sb) : "l"(sm1));

    const int r  = tid >> 1;
    const int hw = (tid & 1);
    const uint32_t dstw = (uint32_t)(r * WS1 + hw * 8);
    const size_t   srcw = (size_t)r * (DIM / 2) + hw * 8;

    const int a_row = (lane & 7) + ((lane >> 3) & 1) * 8;
    const int a_kw  = ((lane >> 4) & 1) * 4;
    const int b_row = (lane & 7) + ((lane >> 4) & 1) * 8;
    const int b_kw  = ((lane >> 3) & 1) * 4;

    float acc[4][4][4];
#pragma unroll
    for (int i = 0; i < 4; i++)
#pragma unroll
        for (int j = 0; j < 4; j++)
#pragma unroll
            for (int q = 0; q < 4; q++) acc[i][j][q] = 0.0f;

    auto issue = [&](int ch, int s) {
        const uint32_t d0 = sb + (uint32_t)(s * STAGE_W + dstw) * 4;
        const size_t   sw = srcw + (size_t)ch * 16;
        CP16(d0 + 0 * TILE_W * 4,      AH + sw);
        CP16(d0 + 0 * TILE_W * 4 + 16, AH + sw + 4);
        CP16(d0 + 1 * TILE_W * 4,      AL + sw);
        CP16(d0 + 1 * TILE_W * 4 + 16, AL + sw + 4);
        CP16(d0 + 2 * TILE_W * 4,      BH + sw);
        CP16(d0 + 2 * TILE_W * 4 + 16, BH + sw + 4);
        CP16(d0 + 3 * TILE_W * 4,      BL + sw);
        CP16(d0 + 3 * TILE_W * 4 + 16, BL + sw + 4);
        CP_COMMIT();
    };

    issue(0, 0);

#pragma unroll 1
    for (int ch = 0; ch < 4; ch++) {
        if (ch < 3) issue(ch + 1, (ch + 1) & 1);
        if (ch < 3) { CP_WAIT1(); } else { CP_WAIT0(); }
        __syncthreads();

        const uint32_t stg = sb + (uint32_t)((ch & 1) * STAGE_W) * 4;
        const uint32_t bAH = stg;
        const uint32_t bAL = stg + TILE_W * 4;
        const uint32_t bBH = stg + 2 * TILE_W * 4;
        const uint32_t bBL = stg + 3 * TILE_W * 4;

#pragma unroll
        for (int ks = 0; ks < 2; ks++) {
            const int k0 = ks * 8;
            uint32_t ah[4][4], al[4][4];
#pragma unroll
            for (int mt = 0; mt < 4; mt++) {
                const uint32_t off =
                    (uint32_t)((wm + mt * 16 + a_row) * WS1 + k0 + a_kw) * 4;
                LDSM4(ah[mt][0], ah[mt][1], ah[mt][2], ah[mt][3], bAH + off);
                LDSM4(al[mt][0], al[mt][1], al[mt][2], al[mt][3], bAL + off);
            }
            uint32_t bh[4][2], bl[4][2];
#pragma unroll
            for (int np = 0; np < 2; np++) {
                const uint32_t off =
                    (uint32_t)((wn + np * 16 + b_row) * WS1 + k0 + b_kw) * 4;
                LDSM4(bh[2 * np][0], bh[2 * np][1], bh[2 * np + 1][0], bh[2 * np + 1][1],
                      bBH + off);
                LDSM4(bl[2 * np][0], bl[2 * np][1], bl[2 * np + 1][0], bl[2 * np + 1][1],
                      bBL + off);
            }
#pragma unroll
            for (int nt = 0; nt < 4; nt++) {
#pragma unroll
                for (int mt = 0; mt < 4; mt++) {
                    MMA_BF16(acc[mt][nt], ah[mt], bh[nt][0], bh[nt][1]);
                    MMA_BF16(acc[mt][nt], ah[mt], bl[nt][0], bl[nt][1]);
                    MMA_BF16(acc[mt][nt], al[mt], bh[nt][0], bh[nt][1]);
                }
            }
        }
        __syncthreads();
    }

    // ---- epilogue: exp; tile row max+sum; fp16 normalized TRANSPOSED store
    float*    s_max  = (float*)sm1;
    float*    s_part = (float*)sm1 + 512;
    uint32_t* s_T    = sm1 + 1024;           // 128*68 words

#pragma unroll
    for (int mt = 0; mt < 4; mt++)
#pragma unroll
        for (int nt = 0; nt < 4; nt++)
#pragma unroll
            for (int q = 0; q < 4; q++) acc[mt][nt][q] = __expf(acc[mt][nt][q]);

#pragma unroll
    for (int mt = 0; mt < 4; mt++) {
        float m0v = 0.f, m1v = 0.f, s0 = 0.f, s1 = 0.f;
#pragma unroll
        for (int nt = 0; nt < 4; nt++) {
            m0v = fmaxf(m0v, fmaxf(acc[mt][nt][0], acc[mt][nt][1]));
            m1v = fmaxf(m1v, fmaxf(acc[mt][nt][2], acc[mt][nt][3]));
            s0 += acc[mt][nt][0] + acc[mt][nt][1];
            s1 += acc[mt][nt][2] + acc[mt][nt][3];
        }
        m0v = fmaxf(m0v, __shfl_xor_sync(0xffffffffu, m0v, 1));
        m0v = fmaxf(m0v, __shfl_xor_sync(0xffffffffu, m0v, 2));
        m1v = fmaxf(m1v, __shfl_xor_sync(0xffffffffu, m1v, 1));
        m1v = fmaxf(m1v, __shfl_xor_sync(0xffffffffu, m1v, 2));
        s0 += __shfl_xor_sync(0xffffffffu, s0, 1);
        s0 += __shfl_xor_sync(0xffffffffu, s0, 2);
        s1 += __shfl_xor_sync(0xffffffffu, s1, 1);
        s1 += __shfl_xor_sync(0xffffffffu, s1, 2);
        if (lk4 == 0) {
            const int rr = wm + mt * 16 + lr4;
            s_max[(wid & 3) * 128 + rr]      = m0v;
            s_max[(wid & 3) * 128 + rr + 8]  = m1v;
            s_part[(wid & 3) * 128 + rr]     = s0;
            s_part[(wid & 3) * 128 + rr + 8] = s1;
        }
    }
    __syncthreads();

#pragma unroll
    for (int mt = 0; mt < 4; mt++) {
        const int r0i = wm + mt * 16 + lr4;
        const int r1i = r0i + 8;
        const float mu0 = fmaxf(fmaxf(s_max[r0i], s_max[128 + r0i]),
                                fmaxf(s_max[256 + r0i], s_max[384 + r0i]));
        const float mu1 = fmaxf(fmaxf(s_max[r1i], s_max[128 + r1i]),
                                fmaxf(s_max[256 + r1i], s_max[384 + r1i]));
        const float rc0 = 1.0f / mu0;
        const float rc1 = 1.0f / mu1;
#pragma unroll
        for (int nt = 0; nt < 4; nt++) {
            const float v0 = acc[mt][nt][0] * rc0;
            const float v1 = acc[mt][nt][1] * rc0;
            const float v2 = acc[mt][nt][2] * rc1;
            const float v3 = acc[mt][nt][3] * rc1;
            const float p0 = __shfl_xor_sync(0xffffffffu, v0, 4);
            const float p1 = __shfl_xor_sync(0xffffffffu, v1, 4);
            const float p2 = __shfl_xor_sync(0xffffffffu, v2, 4);
            const float p3 = __shfl_xor_sync(0xffffffffu, v3, 4);
            if ((lr4 & 1) == 0) {
                const int m   = wn + nt * 8 + 2 * lk4;
                const int cpl = (wm >> 1) + mt * 8 + (lr4 >> 1);
                s_T[m * 68 + cpl]           = pack_half2(v0, p0);
                s_T[(m + 1) * 68 + cpl]     = pack_half2(v1, p1);
                s_T[m * 68 + cpl + 4]       = pack_half2(v2, p2);
                s_T[(m + 1) * 68 + cpl + 4] = pack_half2(v3, p3);
            }
        }
    }
    __syncthreads();

    {
        const int mr = tid >> 1;
        const int wh = (tid & 1) * 32;
        const size_t gb = ((size_t)(b * LSEQ + m0 + mr)) * 1024 + (size_t)(c0 >> 1) + wh;
#pragma unroll
        for (int i = 0; i < 8; i++)
            *(uint4*)(g_E16 + gb + i * 4) = *(const uint4*)(s_T + mr * 68 + wh + i * 4);
    }
    if (tid < 128) {
        const float tot = (s_part[tid] + s_part[128 + tid]) +
                          (s_part[256 + tid] + s_part[384 + tid]);
        const float mx  = fmaxf(fmaxf(s_max[tid], s_max[128 + tid]),
                                fmaxf(s_max[256 + tid], s_max[384 + tid]));
        const size_t ix = ((size_t)b * LSEQ + c0 + tid) * 16 + blockIdx.x;
        g_esum[ix] = tot;
        g_emax[ix] = mx;
    }
}

// ---------------------------------------------------------------------------
// f16 (inv fused): g_f16[b][mt][cp] = (emax[2cp][mt]/sum[2cp], emax[2cp+1][mt]/sum[2cp+1])
// Each thread recomputes the two row sums (identical order -> deterministic,
// reads are L2-resident). 512 blocks, coalesced writes.
// ---------------------------------------------------------------------------
__global__ __launch_bounds__(256) void f16_kernel() {
    const int i  = blockIdx.x * 256 + threadIdx.x;  // 0..NB*16*1024-1
    const int b  = i >> 14;
    const int mt = (i >> 10) & 15;
    const int cp = i & 1023;
    const size_t c0 = (size_t)b * LSEQ + 2 * cp;

    const float4* p = (const float4*)(g_esum + c0 * 16);
    float4 a = p[0], b4 = p[1], c = p[2], d = p[3];
    const float s0 = (((a.x + a.y) + (a.z + a.w)) + ((b4.x + b4.y) + (b4.z + b4.w)))
                   + (((c.x + c.y) + (c.z + c.w)) + ((d.x + d.y) + (d.z + d.w)));
    const float4* q = (const float4*)(g_esum + (c0 + 1) * 16);
    a = q[0]; b4 = q[1]; c = q[2]; d = q[3];
    const float s1 = (((a.x + a.y) + (a.z + a.w)) + ((b4.x + b4.y) + (b4.z + b4.w)))
                   + (((c.x + c.y) + (c.z + c.w)) + ((d.x + d.y) + (d.z + d.w)));

    const float f0 = g_emax[c0 * 16 + mt]       * (1.0f / s0);
    const float f1 = g_emax[(c0 + 1) * 16 + mt] * (1.0f / s1);
    g_f16[i] = pack_half2(f0, f1);
}

// ---------------------------------------------------------------------------
// GEMM2 (fp16 m16n8k16, split-K, cp.async 2-stage) + FUSED final reduction:
//   part[s][b][m][d] = sum_c Ê[m,c] * (f(c,mt)·ctxT[d,c])
//   last CTA per (b,mt): out = mn - (part0 + part1); resets flag (replay-safe)
// ---------------------------------------------------------------------------
#define A2W (128 * 20)
#define B2W (128 * 20)
#define F2W 32
#define STG2 (A2W + B2W + F2W)               // 5152 words
#define SMEM2_BYTES (2 * STG2 * 4)           // 41216

__global__ __launch_bounds__(256, 2) void gemm2_mma(const float* __restrict__ mn,
                                                    float* __restrict__ out) {
    extern __shared__ uint32_t sm2[];
    const int sp = blockIdx.x;
    const int mt = blockIdx.y;
    const int m0 = mt * 128;
    const int b  = blockIdx.z;
    const int cb2 = sp * (KSPLIT / 2);

    float* PT = g_part + ((size_t)sp * NB + b) * LSEQ * DIM;

    const int tid  = threadIdx.x;
    const int wid  = tid >> 5;
    const int lane = tid & 31;
    const int wm   = (wid >> 2) * 64;
    const int wn   = (wid & 3) * 32;
    const int lr4  = lane >> 2;
    const int lk4  = lane & 3;

    uint32_t sb;
    asm("{ .reg .u64 t; cvta.to.shared.u64 t, %1; cvt.u32.u64 %0, t; }"
        : "=r"(sb) : "l"(sm2));

    const int row  = tid >> 1;
    const int seg8 = (tid & 1) * 8;
    const uint32_t* aSrc = g_E16 + ((size_t)(b * LSEQ + m0 + row)) * 1024 + cb2 + seg8;
    const uint32_t* bSrc = g_Ct16 + ((size_t)(b * DIM + row)) * 1024 + cb2 + seg8;
    const uint32_t* fSrc = g_f16 + ((size_t)(b * 16 + mt)) * 1024 + cb2;
    const uint32_t aDstB = sb + (uint32_t)(row * 20 + seg8) * 4;
    const uint32_t bDstB = sb + (uint32_t)(A2W + row * 20 + seg8) * 4;

    float acc[4][4][4];
#pragma unroll
    for (int i = 0; i < 4; i++)
#pragma unroll
        for (int j = 0; j < 4; j++)
#pragma unroll
            for (int q = 0; q < 4; q++) acc[i][j][q] = 0.0f;

    auto issue = [&](int ch, int s) {
        const uint32_t so = (uint32_t)(s * STG2) * 4;
        CP16(aDstB + so,      aSrc + ch * 16);
        CP16(aDstB + so + 16, aSrc + ch * 16 + 4);
        CP16(bDstB + so,      bSrc + ch * 16);
        CP16(bDstB + so + 16, bSrc + ch * 16 + 4);
        if (tid < 4)
            CP16(sb + so + (uint32_t)(A2W + B2W + tid * 4) * 4, fSrc + ch * 16 + tid * 4);
        CP_COMMIT();
    };

    issue(0, 0);

#pragma unroll 1
    for (int ch = 0; ch < KSPLIT / 32; ch++) {
        if (ch < KSPLIT / 32 - 1) issue(ch + 1, (ch + 1) & 1);
        if (ch < KSPLIT / 32 - 1) { CP_WAIT1(); } else { CP_WAIT0(); }
        __syncthreads();

        const uint32_t* sA = sm2 + (ch & 1) * STG2;
        const uint32_t* sB = sA + A2W;
        const uint32_t* sF = sB + B2W;

#pragma unroll
        for (int ks = 0; ks < 2; ks++) {
            const uint32_t fa = sF[ks * 8 + lk4];
            const uint32_t fb = sF[ks * 8 + lk4 + 4];
            uint32_t a[4][4];
#pragma unroll
            for (int m4 = 0; m4 < 4; m4++) {
                const int base = (wm + m4 * 16 + lr4) * 20 + ks * 8 + lk4;
                a[m4][0] = sA[base];
                a[m4][1] = sA[base + 8 * 20];
                a[m4][2] = sA[base + 4];
                a[m4][3] = sA[base + 8 * 20 + 4];
            }
#pragma unroll
            for (int nt = 0; nt < 4; nt++) {
                const int nb = (wn + nt * 8 + lr4) * 20 + ks * 8 + lk4;
                const uint32_t b0 = hmul2u(sB[nb],     fa);
                const uint32_t b1 = hmul2u(sB[nb + 4], fb);
#pragma unroll
                for (int m4 = 0; m4 < 4; m4++) MMA_F16(acc[m4][nt], a[m4], b0, b1);
            }
        }
        __syncthreads();
    }

#pragma unroll
    for (int m4 = 0; m4 < 4; m4++) {
#pragma unroll
        for (int nt = 0; nt < 4; nt++) {
            const int rowo = m0 + wm + m4 * 16 + lr4;
            const int col  = wn + nt * 8 + 2 * lk4;
            *(float2*)&PT[(size_t)rowo * DIM + col] =
                make_float2(acc[m4][nt][0], acc[m4][nt][1]);
            *(float2*)&PT[(size_t)(rowo + 8) * DIM + col] =
                make_float2(acc[m4][nt][2], acc[m4][nt][3]);
        }
    }

    // ---- fused split-K reduction: last CTA per (b,mt) writes the output
    __syncthreads();
    __shared__ int s_old;
    if (tid == 0) {
        __threadfence();
        s_old = atomicAdd(&g_flag[b * 16 + mt], 1);
    }
    __syncthreads();
    if (s_old == 1) {
        __threadfence();   // acquire: other CTA's part stores are visible
        const float4* p0 = (const float4*)(g_part + (size_t)b * LSEQ * DIM
                                           + (size_t)m0 * DIM);
        const float4* p1 = (const float4*)(g_part + ((size_t)NB + b) * LSEQ * DIM
                                           + (size_t)m0 * DIM);
        const float4* pm = (const float4*)(mn + ((size_t)b * LSEQ + m0) * DIM);
        float4* po = (float4*)(out + ((size_t)b * LSEQ + m0) * DIM);
#pragma unroll 4
        for (int k = tid; k < 128 * DIM / 4; k += 256) {
            float4 x = p0[k], y = p1[k], m = pm[k];
            po[k] = make_float4(m.x - (x.x + y.x), m.y - (x.y + y.y),
                                m.z - (x.z + y.z), m.w - (x.w + y.w));
        }
        if (tid == 0) g_flag[b * 16 + mt] = 0;   // reset for next replay
    }
}

extern "C" void kernel_launch(void* const* d_in, const int* in_sizes, int n_in,
                              void* d_out, int out_size) {
    (void)in_sizes; (void)n_in; (void)out_size;
    const float* ctx = (const float*)d_in[0];  // context: (8, 2048, 128) f32
    const float* mn  = (const float*)d_in[1];  // main:    (8, 2048, 128) f32
    float* out = (float*)d_out;                // (8, 2048, 128) f32

    cudaFuncSetAttribute(gemm1_mma, cudaFuncAttributeMaxDynamicSharedMemorySize, SMEM1_BYTES);
    cudaFuncSetAttribute(gemm2_mma, cudaFuncAttributeMaxDynamicSharedMemorySize, SMEM2_BYTES);

    precvt_kernel<<<NB * LSEQ * DIM / 4 / 256, 256>>>(ctx, mn);
    tctx_kernel<<<NB * 16, 256>>>(ctx);

    dim3 g1(LSEQ / 128, LSEQ / 128, NB);       // 16 x 16 x 8
    gemm1_mma<<<g1, 256, SMEM1_BYTES>>>();

    f16_kernel<<<NB * 16 * 1024 / 256, 256>>>();

    dim3 g2(NSPLIT, LSEQ / 128, NB);           // 2 x 16 x 8
    gemm2_mma<<<g2, 256, SMEM2_BYTES>>>(mn, out);
}

// round 15
// speedup vs baseline: 1.0364x; 1.0364x over previous
#include <cuda_runtime.h>
#include <cuda_bf16.h>
#include <cuda_fp16.h>
#include <cstdint>

#define NB 8
#define LSEQ 2048
#define DIM 128
#define NSPLIT 2
#define KSPLIT (LSEQ / NSPLIT)   // 1024

// 64 MiB: Ê fp16 pairs, layout [b][m][cpair]
static __device__ uint32_t g_E16[(size_t)NB * LSEQ * 1024];
// 4 MiB: ctx transposed fp16 pairs [b][d][cpair]
static __device__ uint32_t g_Ct16[(size_t)NB * DIM * 1024];
// 16 MiB split-K partials of GEMM2: [split][b][m][d]
static __device__ float g_part[(size_t)NSPLIT * NB * LSEQ * DIM];
// per-(b,c)-row per-m-tile partial sums and maxes of E
static __device__ float g_esum[(size_t)NB * LSEQ * 16];
static __device__ float g_emax[(size_t)NB * LSEQ * 16];
// 1/sum(E) per (b,c)
static __device__ float g_finv[(size_t)NB * LSEQ];
// fp16 f-pairs: f(c,mt)=mu(c,mt)/sum(c); word [b][mt][cpair]
static __device__ uint32_t g_f16[(size_t)NB * 16 * 1024];
// pre-converted bf16 hi/lo limb words for gemm1 inputs
#define NWORDS ((size_t)NB * LSEQ * DIM / 2)
static __device__ uint32_t g_cth[NWORDS];
static __device__ uint32_t g_ctl[NWORDS];
static __device__ uint32_t g_mnh[NWORDS];
static __device__ uint32_t g_mnl[NWORDS];

__device__ __forceinline__ uint32_t pack_bf16x2(float x, float y) {
    __nv_bfloat162 h = __floats2bfloat162_rn(x, y);
    return *reinterpret_cast<uint32_t*>(&h);
}
__device__ __forceinline__ uint32_t pack_half2(float x, float y) {
    __half2 h = __floats2half2_rn(x, y);
    return *reinterpret_cast<uint32_t*>(&h);
}
__device__ __forceinline__ uint32_t hmul2u(uint32_t a, uint32_t b) {
    __half2 r = __hmul2(*reinterpret_cast<__half2*>(&a), *reinterpret_cast<__half2*>(&b));
    return *reinterpret_cast<uint32_t*>(&r);
}

#define MMA_BF16(d, a, b0v, b1v)                                               \
    asm volatile(                                                              \
        "mma.sync.aligned.m16n8k16.row.col.f32.bf16.bf16.f32 "                 \
        "{%0,%1,%2,%3}, {%4,%5,%6,%7}, {%8,%9}, {%0,%1,%2,%3};"                \
        : "+f"((d)[0]), "+f"((d)[1]), "+f"((d)[2]), "+f"((d)[3])               \
        : "r"((a)[0]), "r"((a)[1]), "r"((a)[2]), "r"((a)[3]),                  \
          "r"(b0v), "r"(b1v))

#define MMA_F16(d, a, b0v, b1v)                                                \
    asm volatile(                                                              \
        "mma.sync.aligned.m16n8k16.row.col.f32.f16.f16.f32 "                   \
        "{%0,%1,%2,%3}, {%4,%5,%6,%7}, {%8,%9}, {%0,%1,%2,%3};"                \
        : "+f"((d)[0]), "+f"((d)[1]), "+f"((d)[2]), "+f"((d)[3])               \
        : "r"((a)[0]), "r"((a)[1]), "r"((a)[2]), "r"((a)[3]),                  \
          "r"(b0v), "r"(b1v))

#define LDSM4(r0, r1, r2, r3, addr)                                            \
    asm volatile("ldmatrix.sync.aligned.m8n8.x4.shared.b16 {%0,%1,%2,%3}, [%4];" \
                 : "=r"(r0), "=r"(r1), "=r"(r2), "=r"(r3) : "r"(addr))

#define CP16(dst, src)                                                         \
    asm volatile("cp.async.cg.shared.global [%0], [%1], 16;"                   \
                 :: "r"(dst), "l"(src))
#define CP_COMMIT() asm volatile("cp.async.commit_group;")
#define CP_WAIT1() asm volatile("cp.async.wait_group 1;")
#define CP_WAIT0() asm volatile("cp.async.wait_group 0;")

// ---------------------------------------------------------------------------
// precvt: split ctx/main into bf16 hi + lo limb word arrays (gemm1 inputs).
// ---------------------------------------------------------------------------
__global__ __launch_bounds__(256) void precvt_kernel(const float* __restrict__ ctx,
                                                     const float* __restrict__ mn) {
    const size_t i = (size_t)blockIdx.x * 256 + threadIdx.x;  // float4 index
    {
        float4 v = ((const float4*)ctx)[i];
        uint32_t h01 = pack_bf16x2(v.x, v.y);
        uint32_t h23 = pack_bf16x2(v.z, v.w);
        __nv_bfloat162 hp = *(__nv_bfloat162*)&h01;
        __nv_bfloat162 hq = *(__nv_bfloat162*)&h23;
        g_cth[2 * i]     = h01;
        g_cth[2 * i + 1] = h23;
        g_ctl[2 * i]     = pack_bf16x2(v.x - __bfloat162float(hp.x),
                                       v.y - __bfloat162float(hp.y));
        g_ctl[2 * i + 1] = pack_bf16x2(v.z - __bfloat162float(hq.x),
                                       v.w - __bfloat162float(hq.y));
    }
    {
        float4 v = ((const float4*)mn)[i];
        uint32_t h01 = pack_bf16x2(v.x, v.y);
        uint32_t h23 = pack_bf16x2(v.z, v.w);
        __nv_bfloat162 hp = *(__nv_bfloat162*)&h01;
        __nv_bfloat162 hq = *(__nv_bfloat162*)&h23;
        g_mnh[2 * i]     = h01;
        g_mnh[2 * i + 1] = h23;
        g_mnl[2 * i]     = pack_bf16x2(v.x - __bfloat162float(hp.x),
                                       v.y - __bfloat162float(hp.y));
        g_mnl[2 * i + 1] = pack_bf16x2(v.z - __bfloat162float(hq.x),
                                       v.w - __bfloat162float(hq.y));
    }
}

// ---------------------------------------------------------------------------
// tctx: g_Ct16[b][d][cp] = (half(ctx[b,2cp,d]), half(ctx[b,2cp+1,d]))
// ---------------------------------------------------------------------------
__global__ __launch_bounds__(256) void tctx_kernel(const float* __restrict__ ctx) {
    const int b  = blockIdx.x >> 4;
    const int ct = blockIdx.x & 15;
    const int t  = threadIdx.x;
    const int cp = t & 63;
    const int d0 = (t >> 6) * 32;
    const float* r0 = ctx + ((size_t)b * LSEQ + ct * 128 + 2 * cp) * DIM + d0;
    const float* r1 = r0 + DIM;
#pragma unroll
    for (int j = 0; j < 8; j++) {
        float4 a = ((const float4*)r0)[j];
        float4 c = ((const float4*)r1)[j];
        const size_t base = ((size_t)(b * DIM + d0 + 4 * j)) * 1024 + ct * 64 + cp;
        g_Ct16[base]        = pack_half2(a.x, c.x);
        g_Ct16[base + 1024] = pack_half2(a.y, c.y);
        g_Ct16[base + 2048] = pack_half2(a.z, c.z);
        g_Ct16[base + 3072] = pack_half2(a.w, c.w);
    }
}

// ---------------------------------------------------------------------------
// GEMM1 (bf16 m16n8k16 3x split, cp.async 2-stage, ldmatrix fragments).
// Epilogue: exp, per-tile row max/sum, store Ê fp16 TRANSPOSED [m][cpair].
// ---------------------------------------------------------------------------
#define WS1 20
#define TILE_W (128 * WS1)
#define STAGE_W (4 * TILE_W)
#define SMEM1_BYTES (2 * STAGE_W * 4)        // 81920

__global__ __launch_bounds__(256, 2) void gemm1_mma() {
    extern __shared__ uint32_t sm1[];
    const int tid  = threadIdx.x;
    const int wid  = tid >> 5;
    const int lane = tid & 31;
    const int wm   = (wid >> 2) * 64;
    const int wn   = (wid & 3) * 32;
    const int lr4  = lane >> 2;
    const int lk4  = lane & 3;

    const int b  = blockIdx.z;
    const int c0 = blockIdx.y * 128;
    const int m0 = blockIdx.x * 128;

    const uint32_t* AH = g_cth + ((size_t)b * LSEQ + c0) * (DIM / 2);
    const uint32_t* AL = g_ctl + ((size_t)b * LSEQ + c0) * (DIM / 2);
    const uint32_t* BH = g_mnh + ((size_t)b * LSEQ + m0) * (DIM / 2);
    const uint32_t* BL = g_mnl + ((size_t)b * LSEQ + m0) * (DIM / 2);

    uint32_t sb;
    asm("{ .reg .u64 t; cvta.to.shared.u64 t, %1; cvt.u32.u64 %0, t; }"
        : "=r"(sb) : "l"(sm1));

    const int r  = tid >> 1;
    const int hw = (tid & 1);
    const uint32_t dstw = (uint32_t)(r * WS1 + hw * 8);
    const size_t   srcw = (size_t)r * (DIM / 2) + hw * 8;

    const int a_row = (lane & 7) + ((lane >> 3) & 1) * 8;
    const int a_kw  = ((lane >> 4) & 1) * 4;
    const int b_row = (lane & 7) + ((lane >> 4) & 1) * 8;
    const int b_kw  = ((lane >> 3) & 1) * 4;

    float acc[4][4][4];
#pragma unroll
    for (int i = 0; i < 4; i++)
#pragma unroll
        for (int j = 0; j < 4; j++)
#pragma unroll
            for (int q = 0; q < 4; q++) acc[i][j][q] = 0.0f;

    auto issue = [&](int ch, int s) {
        const uint32_t d0 = sb + (uint32_t)(s * STAGE_W + dstw) * 4;
        const size_t   sw = srcw + (size_t)ch * 16;
        CP16(d0 + 0 * TILE_W * 4,      AH + sw);
        CP16(d0 + 0 * TILE_W * 4 + 16, AH + sw + 4);
        CP16(d0 + 1 * TILE_W * 4,      AL + sw);
        CP16(d0 + 1 * TILE_W * 4 + 16, AL + sw + 4);
        CP16(d0 + 2 * TILE_W * 4,      BH + sw);
        CP16(d0 + 2 * TILE_W * 4 + 16, BH + sw + 4);
        CP16(d0 + 3 * TILE_W * 4,      BL + sw);
        CP16(d0 + 3 * TILE_W * 4 + 16, BL + sw + 4);
        CP_COMMIT();
    };

    issue(0, 0);

#pragma unroll 1
    for (int ch = 0; ch < 4; ch++) {
        if (ch < 3) issue(ch + 1, (ch + 1) & 1);
        if (ch < 3) { CP_WAIT1(); } else { CP_WAIT0(); }
        __syncthreads();

        const uint32_t stg = sb + (uint32_t)((ch & 1) * STAGE_W) * 4;
        const uint32_t bAH = stg;
        const uint32_t bAL = stg + TILE_W * 4;
        const uint32_t bBH = stg + 2 * TILE_W * 4;
        const uint32_t bBL = stg + 3 * TILE_W * 4;

#pragma unroll
        for (int ks = 0; ks < 2; ks++) {
            const int k0 = ks * 8;
            uint32_t ah[4][4], al[4][4];
#pragma unroll
            for (int mt = 0; mt < 4; mt++) {
                const uint32_t off =
                    (uint32_t)((wm + mt * 16 + a_row) * WS1 + k0 + a_kw) * 4;
                LDSM4(ah[mt][0], ah[mt][1], ah[mt][2], ah[mt][3], bAH + off);
                LDSM4(al[mt][0], al[mt][1], al[mt][2], al[mt][3], bAL + off);
            }
            uint32_t bh[4][2], bl[4][2];
#pragma unroll
            for (int np = 0; np < 2; np++) {
                const uint32_t off =
                    (uint32_t)((wn + np * 16 + b_row) * WS1 + k0 + b_kw) * 4;
                LDSM4(bh[2 * np][0], bh[2 * np][1], bh[2 * np + 1][0], bh[2 * np + 1][1],
                      bBH + off);
                LDSM4(bl[2 * np][0], bl[2 * np][1], bl[2 * np + 1][0], bl[2 * np + 1][1],
                      bBL + off);
            }
#pragma unroll
            for (int nt = 0; nt < 4; nt++) {
#pragma unroll
                for (int mt = 0; mt < 4; mt++) {
                    MMA_BF16(acc[mt][nt], ah[mt], bh[nt][0], bh[nt][1]);
                    MMA_BF16(acc[mt][nt], ah[mt], bl[nt][0], bl[nt][1]);
                    MMA_BF16(acc[mt][nt], al[mt], bh[nt][0], bh[nt][1]);
                }
            }
        }
        __syncthreads();
    }

    // ---- epilogue: exp; tile row max+sum; fp16 normalized TRANSPOSED store
    float*    s_max  = (float*)sm1;
    float*    s_part = (float*)sm1 + 512;
    uint32_t* s_T    = sm1 + 1024;           // 128*68 words

#pragma unroll
    for (int mt = 0; mt < 4; mt++)
#pragma unroll
        for (int nt = 0; nt < 4; nt++)
#pragma unroll
            for (int q = 0; q < 4; q++) acc[mt][nt][q] = __expf(acc[mt][nt][q]);

#pragma unroll
    for (int mt = 0; mt < 4; mt++) {
        float m0v = 0.f, m1v = 0.f, s0 = 0.f, s1 = 0.f;
#pragma unroll
        for (int nt = 0; nt < 4; nt++) {
            m0v = fmaxf(m0v, fmaxf(acc[mt][nt][0], acc[mt][nt][1]));
            m1v = fmaxf(m1v, fmaxf(acc[mt][nt][2], acc[mt][nt][3]));
            s0 += acc[mt][nt][0] + acc[mt][nt][1];
            s1 += acc[mt][nt][2] + acc[mt][nt][3];
        }
        m0v = fmaxf(m0v, __shfl_xor_sync(0xffffffffu, m0v, 1));
        m0v = fmaxf(m0v, __shfl_xor_sync(0xffffffffu, m0v, 2));
        m1v = fmaxf(m1v, __shfl_xor_sync(0xffffffffu, m1v, 1));
        m1v = fmaxf(m1v, __shfl_xor_sync(0xffffffffu, m1v, 2));
        s0 += __shfl_xor_sync(0xffffffffu, s0, 1);
        s0 += __shfl_xor_sync(0xffffffffu, s0, 2);
        s1 += __shfl_xor_sync(0xffffffffu, s1, 1);
        s1 += __shfl_xor_sync(0xffffffffu, s1, 2);
        if (lk4 == 0) {
            const int rr = wm + mt * 16 + lr4;
            s_max[(wid & 3) * 128 + rr]      = m0v;
            s_max[(wid & 3) * 128 + rr + 8]  = m1v;
            s_part[(wid & 3) * 128 + rr]     = s0;
            s_part[(wid & 3) * 128 + rr + 8] = s1;
        }
    }
    __syncthreads();

#pragma unroll
    for (int mt = 0; mt < 4; mt++) {
        const int r0i = wm + mt * 16 + lr4;
        const int r1i = r0i + 8;
        const float mu0 = fmaxf(fmaxf(s_max[r0i], s_max[128 + r0i]),
                                fmaxf(s_max[256 + r0i], s_max[384 + r0i]));
        const float mu1 = fmaxf(fmaxf(s_max[r1i], s_max[128 + r1i]),
                                fmaxf(s_max[256 + r1i], s_max[384 + r1i]));
        const float rc0 = 1.0f / mu0;
        const float rc1 = 1.0f / mu1;
#pragma unroll
        for (int nt = 0; nt < 4; nt++) {
            const float v0 = acc[mt][nt][0] * rc0;
            const float v1 = acc[mt][nt][1] * rc0;
            const float v2 = acc[mt][nt][2] * rc1;
            const float v3 = acc[mt][nt][3] * rc1;
            const float p0 = __shfl_xor_sync(0xffffffffu, v0, 4);
            const float p1 = __shfl_xor_sync(0xffffffffu, v1, 4);
            const float p2 = __shfl_xor_sync(0xffffffffu, v2, 4);
            const float p3 = __shfl_xor_sync(0xffffffffu, v3, 4);
            if ((lr4 & 1) == 0) {
                const int m   = wn + nt * 8 + 2 * lk4;
                const int cpl = (wm >> 1) + mt * 8 + (lr4 >> 1);
                s_T[m * 68 + cpl]           = pack_half2(v0, p0);
                s_T[(m + 1) * 68 + cpl]     = pack_half2(v1, p1);
                s_T[m * 68 + cpl + 4]       = pack_half2(v2, p2);
                s_T[(m + 1) * 68 + cpl + 4] = pack_half2(v3, p3);
            }
        }
    }
    __syncthreads();

    {
        const int mr = tid >> 1;
        const int wh = (tid & 1) * 32;
        const size_t gb = ((size_t)(b * LSEQ + m0 + mr)) * 1024 + (size_t)(c0 >> 1) + wh;
#pragma unroll
        for (int i = 0; i < 8; i++)
            *(uint4*)(g_E16 + gb + i * 4) = *(const uint4*)(s_T + mr * 68 + wh + i * 4);
    }
    if (tid < 128) {
        const float tot = (s_part[tid] + s_part[128 + tid]) +
                          (s_part[256 + tid] + s_part[384 + tid]);
        const float mx  = fmaxf(fmaxf(s_max[tid], s_max[128 + tid]),
                                fmaxf(s_max[256 + tid], s_max[384 + tid]));
        const size_t ix = ((size_t)b * LSEQ + c0 + tid) * 16 + blockIdx.x;
        g_esum[ix] = tot;
        g_emax[ix] = mx;
    }
}

// ---------------------------------------------------------------------------
// inv (warp-parallel): 16 threads per (b,c) row; shuffle-tree reduce of the
// 16 tile-sums; lane 0 of each group writes 1/sum. 1024 blocks.
// ---------------------------------------------------------------------------
__global__ __launch_bounds__(256) void inv_kernel() {
    const int gid = blockIdx.x * 256 + threadIdx.x;   // 0..NB*LSEQ*16-1
    const int row = gid >> 4;
    const int t   = gid & 15;
    float v = g_esum[(size_t)row * 16 + t];
    v += __shfl_xor_sync(0xffffffffu, v, 8);
    v += __shfl_xor_sync(0xffffffffu, v, 4);
    v += __shfl_xor_sync(0xffffffffu, v, 2);
    v += __shfl_xor_sync(0xffffffffu, v, 1);
    if (t == 0) g_finv[row] = 1.0f / v;
}

// ---------------------------------------------------------------------------
// f16: g_f16[b][mt][cp] = (emax[2cp][mt]*finv[2cp], emax[2cp+1][mt]*finv[2cp+1])
// one thread per output word; 512 blocks, coalesced writes.
// ---------------------------------------------------------------------------
__global__ __launch_bounds__(256) void f16_kernel() {
    const int i  = blockIdx.x * 256 + threadIdx.x;  // 0..NB*16*1024-1
    const int b  = i >> 14;
    const int mt = (i >> 10) & 15;
    const int cp = i & 1023;
    const size_t c0 = (size_t)b * LSEQ + 2 * cp;
    const float f0 = g_emax[c0 * 16 + mt]       * g_finv[c0];
    const float f1 = g_emax[(c0 + 1) * 16 + mt] * g_finv[c0 + 1];
    g_f16[i] = pack_half2(f0, f1);
}

// ---------------------------------------------------------------------------
// GEMM2 (fp16 m16n8k16, split-K, cp.async 2-stage):
//   part[s][b][m][d] = sum_c Ê[m,c] * (f(c,mt)·ctxT[d,c])   (f applied to B)
// ---------------------------------------------------------------------------
#define A2W (128 * 20)
#define B2W (128 * 20)
#define F2W 32
#define STG2 (A2W + B2W + F2W)               // 5152 words
#define SMEM2_BYTES (2 * STG2 * 4)           // 41216

__global__ __launch_bounds__(256, 2) void gemm2_mma() {
    extern __shared__ uint32_t sm2[];
    const int sp = blockIdx.x;
    const int mt = blockIdx.y;
    const int m0 = mt * 128;
    const int b  = blockIdx.z;
    const int cb2 = sp * (KSPLIT / 2);

    float* PT = g_part + ((size_t)sp * NB + b) * LSEQ * DIM;

    const int tid  = threadIdx.x;
    const int wid  = tid >> 5;
    const int lane = tid & 31;
    const int wm   = (wid >> 2) * 64;
    const int wn   = (wid & 3) * 32;
    const int lr4  = lane >> 2;
    const int lk4  = lane & 3;

    uint32_t sb;
    asm("{ .reg .u64 t; cvta.to.shared.u64 t, %1; cvt.u32.u64 %0, t; }"
        : "=r"(sb) : "l"(sm2));

    const int row  = tid >> 1;
    const int seg8 = (tid & 1) * 8;
    const uint32_t* aSrc = g_E16 + ((size_t)(b * LSEQ + m0 + row)) * 1024 + cb2 + seg8;
    const uint32_t* bSrc = g_Ct16 + ((size_t)(b * DIM + row)) * 1024 + cb2 + seg8;
    const uint32_t* fSrc = g_f16 + ((size_t)(b * 16 + mt)) * 1024 + cb2;
    const uint32_t aDstB = sb + (uint32_t)(row * 20 + seg8) * 4;
    const uint32_t bDstB = sb + (uint32_t)(A2W + row * 20 + seg8) * 4;

    float acc[4][4][4];
#pragma unroll
    for (int i = 0; i < 4; i++)
#pragma unroll
        for (int j = 0; j < 4; j++)
#pragma unroll
            for (int q = 0; q < 4; q++) acc[i][j][q] = 0.0f;

    auto issue = [&](int ch, int s) {
        const uint32_t so = (uint32_t)(s * STG2) * 4;
        CP16(aDstB + so,      aSrc + ch * 16);
        CP16(aDstB + so + 16, aSrc + ch * 16 + 4);
        CP16(bDstB + so,      bSrc + ch * 16);
        CP16(bDstB + so + 16, bSrc + ch * 16 + 4);
        if (tid < 4)
            CP16(sb + so + (uint32_t)(A2W + B2W + tid * 4) * 4, fSrc + ch * 16 + tid * 4);
        CP_COMMIT();
    };

    issue(0, 0);

#pragma unroll 1
    for (int ch = 0; ch < KSPLIT / 32; ch++) {
        if (ch < KSPLIT / 32 - 1) issue(ch + 1, (ch + 1) & 1);
        if (ch < KSPLIT / 32 - 1) { CP_WAIT1(); } else { CP_WAIT0(); }
        __syncthreads();

        const uint32_t* sA = sm2 + (ch & 1) * STG2;
        const uint32_t* sB = sA + A2W;
        const uint32_t* sF = sB + B2W;

#pragma unroll
        for (int ks = 0; ks < 2; ks++) {
            const uint32_t fa = sF[ks * 8 + lk4];
            const uint32_t fb = sF[ks * 8 + lk4 + 4];
            uint32_t a[4][4];
#pragma unroll
            for (int m4 = 0; m4 < 4; m4++) {
                const int base = (wm + m4 * 16 + lr4) * 20 + ks * 8 + lk4;
                a[m4][0] = sA[base];
                a[m4][1] = sA[base + 8 * 20];
                a[m4][2] = sA[base + 4];
                a[m4][3] = sA[base + 8 * 20 + 4];
            }
#pragma unroll
            for (int nt = 0; nt < 4; nt++) {
                const int nb = (wn + nt * 8 + lr4) * 20 + ks * 8 + lk4;
                const uint32_t b0 = hmul2u(sB[nb],     fa);
                const uint32_t b1 = hmul2u(sB[nb + 4], fb);
#pragma unroll
                for (int m4 = 0; m4 < 4; m4++) MMA_F16(acc[m4][nt], a[m4], b0, b1);
            }
        }
        __syncthreads();
    }

#pragma unroll
    for (int m4 = 0; m4 < 4; m4++) {
#pragma unroll
        for (int nt = 0; nt < 4; nt++) {
            const int rowo = m0 + wm + m4 * 16 + lr4;
            const int col  = wn + nt * 8 + 2 * lk4;
            *(float2*)&PT[(size_t)rowo * DIM + col] =
                make_float2(acc[m4][nt][0], acc[m4][nt][1]);
            *(float2*)&PT[(size_t)(rowo + 8) * DIM + col] =
                make_float2(acc[m4][nt][2], acc[m4][nt][3]);
        }
    }
}

// ---------------------------------------------------------------------------
// Reduce: out[b,m,d] = main[b,m,d] - sum_s part[s][b][m][d]
// ---------------------------------------------------------------------------
__global__ __launch_bounds__(256) void reduce_kernel(const float* __restrict__ mn,
                                                     float* __restrict__ out) {
    const size_t i = (size_t)blockIdx.x * blockDim.x + threadIdx.x;
    const size_t stride4 = (size_t)NB * LSEQ * DIM / 4;
    float4 m = ((const float4*)mn)[i];
    float4 s = make_float4(0.f, 0.f, 0.f, 0.f);
    const float4* p4 = (const float4*)g_part;
#pragma unroll
    for (int sp = 0; sp < NSPLIT; sp++) {
        float4 v = p4[(size_t)sp * stride4 + i];
        s.x += v.x; s.y += v.y; s.z += v.z; s.w += v.w;
    }
    ((float4*)out)[i] = make_float4(m.x - s.x, m.y - s.y, m.z - s.z, m.w - s.w);
}

extern "C" void kernel_launch(void* const* d_in, const int* in_sizes, int n_in,
                              void* d_out, int out_size) {
    (void)in_sizes; (void)n_in; (void)out_size;
    const float* ctx = (const float*)d_in[0];  // context: (8, 2048, 128) f32
    const float* mn  = (const float*)d_in[1];  // main:    (8, 2048, 128) f32
    float* out = (float*)d_out;                // (8, 2048, 128) f32

    cudaFuncSetAttribute(gemm1_mma, cudaFuncAttributeMaxDynamicSharedMemorySize, SMEM1_BYTES);
    cudaFuncSetAttribute(gemm2_mma, cudaFuncAttributeMaxDynamicSharedMemorySize, SMEM2_BYTES);

    precvt_kernel<<<NB * LSEQ * DIM / 4 / 256, 256>>>(ctx, mn);
    tctx_kernel<<<NB * 16, 256>>>(ctx);

    dim3 g1(LSEQ / 128, LSEQ / 128, NB);       // 16 x 16 x 8
    gemm1_mma<<<g1, 256, SMEM1_BYTES>>>();

    inv_kernel<<<NB * LSEQ * 16 / 256, 256>>>();
    f16_kernel<<<NB * 16 * 1024 / 256, 256>>>();

    dim3 g2(NSPLIT, LSEQ / 128, NB);           // 2 x 16 x 8
    gemm2_mma<<<g2, 256, SMEM2_BYTES>>>();

    const int n4 = NB * LSEQ * DIM / 4;        // 524288 float4
    reduce_kernel<<<n4 / 256, 256>>>(mn, out);
}